// round 6
// baseline (speedup 1.0000x reference)
#include <cuda_runtime.h>
#include <cstdint>
#include <cstddef>

#define FEAT 128
#define NUM_BASES 4
#define NCT 5
#define MAX_NODES 100000
#define MAX_EDGES 1000000
#define NB 1024            // buckets (src >> 7), 782 used
#define BSHIFT 7

typedef unsigned int u32;

// scratch
__device__ float g_proj[(size_t)MAX_NODES * NUM_BASES * FEAT];
__device__ float g_wt[NCT * FEAT * FEAT];   // [ct][n][k] = W_ct[k][n]
__device__ int   g_cnt[NB];
__device__ int   g_off[NB];
__device__ int   g_pk[MAX_EDGES];           // (src<<3)|rel, bucket-sorted
__device__ int   g_pd[MAX_EDGES];           // dst, bucket-sorted

__device__ __forceinline__ u32 tf32r(float x) {
    u32 r; asm("cvt.rna.tf32.f32 %0, %1;" : "=r"(r) : "f"(x)); return r;
}
__device__ __forceinline__ void mma_tf32(float* d, const u32* a, const u32* b) {
    asm("mma.sync.aligned.m16n8k8.row.col.f32.tf32.tf32.f32 "
        "{%0,%1,%2,%3}, {%4,%5,%6,%7}, {%8,%9}, {%0,%1,%2,%3};"
        : "+f"(d[0]), "+f"(d[1]), "+f"(d[2]), "+f"(d[3])
        : "r"(a[0]), "r"(a[1]), "r"(a[2]), "r"(a[3]), "r"(b[0]), "r"(b[1]));
}
__device__ __forceinline__ u32 smem_u32(const void* p) {
    u32 a;
    asm("{ .reg .u64 t; cvta.to.shared.u64 t, %1; cvt.u32.u64 %0, t; }" : "=r"(a) : "l"(p));
    return a;
}
__device__ __forceinline__ void ldsm4(u32& r0, u32& r1, u32& r2, u32& r3, u32 addr) {
    asm volatile("ldmatrix.sync.aligned.m8n8.x4.shared.b16 {%0,%1,%2,%3}, [%4];"
                 : "=r"(r0), "=r"(r1), "=r"(r2), "=r"(r3) : "r"(addr));
}

// ---------------- kernel 0: transpose weights into g_wt ----------------
__global__ void transpose_w_kernel(const float* __restrict__ weight,
                                   const float* __restrict__ root)
{
    __shared__ float tile[32][33];
    const int ct = blockIdx.z;
    const float* __restrict__ src = (ct < NUM_BASES) ? (weight + (size_t)ct * FEAT * FEAT)
                                                     : root;
    const int n0 = blockIdx.x * 32, k0 = blockIdx.y * 32;
    const int tx = threadIdx.x, ty = threadIdx.y;  // 32 x 8
#pragma unroll
    for (int j = 0; j < 32; j += 8)
        tile[ty + j][tx] = src[(size_t)(k0 + ty + j) * FEAT + n0 + tx];
    __syncthreads();
    float* __restrict__ dst = g_wt + (size_t)ct * FEAT * FEAT;
#pragma unroll
    for (int j = 0; j < 32; j += 8)
        dst[(size_t)(n0 + ty + j) * FEAT + k0 + tx] = tile[tx][ty + j];
}

// ---------------- edge bucket sort (by src >> BSHIFT) ----------------
__global__ void zero_cnt_kernel()
{
    g_cnt[threadIdx.x] = 0;
}
__global__ void hist_kernel(const int* __restrict__ src, int n_edges)
{
    int i = blockIdx.x * blockDim.x + threadIdx.x;
    if (i < n_edges) atomicAdd(&g_cnt[src[i] >> BSHIFT], 1);
}
__global__ void scan_kernel()
{
    __shared__ int tmp[NB];
    const int t = threadIdx.x;
    const int v = g_cnt[t];
    tmp[t] = v;
    __syncthreads();
    for (int d = 1; d < NB; d <<= 1) {
        int x = (t >= d) ? tmp[t - d] : 0;
        __syncthreads();
        tmp[t] += x;
        __syncthreads();
    }
    g_off[t] = tmp[t] - v;   // exclusive prefix
}
__global__ void scatter_kernel(const int* __restrict__ src,
                               const int* __restrict__ dst,
                               const int* __restrict__ rel, int n_edges)
{
    int i = blockIdx.x * blockDim.x + threadIdx.x;
    if (i >= n_edges) return;
    const int s = src[i];
    const int pos = atomicAdd(&g_off[s >> BSHIFT], 1);
    g_pk[pos] = (s << 3) | rel[i];
    g_pd[pos] = dst[i];
}

// ---------------- kernel 1: split-TF32 mma.sync GEMM (ldmatrix) ----------------
#define BK 32
#define PAD 36
#define TILE_F (128 * PAD)
#define SM_TOTALB (4 * TILE_F * 4)   // 73728 B -> 2 blocks/SM

__global__ void __launch_bounds__(256, 2)
rgcn_gemm_mma_kernel(const float* __restrict__ h,
                     const float* __restrict__ bias,
                     float* __restrict__ out, int n_nodes)
{
    extern __shared__ float smem[];
    float* As_hi = smem;
    float* As_lo = smem + TILE_F;
    float* Bs_hi = smem + 2 * TILE_F;
    float* Bs_lo = smem + 3 * TILE_F;

    const int tid  = threadIdx.x;
    const int lane = tid & 31;
    const int w    = tid >> 5;
    const int g    = lane >> 2;
    const int tig  = lane & 3;
    const int warp_m = w & 3;
    const int warp_n = w >> 2;

    const int ct   = blockIdx.y;
    const int row0 = blockIdx.x * 128;
    const float* __restrict__ Bsrc = g_wt + (size_t)ct * FEAT * FEAT;

    const int a_row_in = lane & 15;
    const int a_kd     = (lane >> 4) * 4;
    const int b_row_in = (lane & 7) + ((lane >> 4) << 3);
    const int b_kd     = ((lane & 15) >> 3) * 4;

    const u32 sAhi = smem_u32(As_hi), sAlo = smem_u32(As_lo);
    const u32 sBhi = smem_u32(Bs_hi), sBlo = smem_u32(Bs_lo);

    float acc[2][8][4];
#pragma unroll
    for (int mi = 0; mi < 2; mi++)
#pragma unroll
        for (int j = 0; j < 8; j++)
#pragma unroll
            for (int c = 0; c < 4; c++) acc[mi][j][c] = 0.f;

    for (int kc = 0; kc < FEAT; kc += BK) {
#pragma unroll
        for (int i = 0; i < 4; i++) {
            const int v  = tid + i * 256;
            const int r  = v >> 3;
            const int c4 = (v & 7) * 4;
            float4 av = make_float4(0.f, 0.f, 0.f, 0.f);
            const int gr = row0 + r;
            if (gr < n_nodes)
                av = *(const float4*)(h + (size_t)gr * FEAT + kc + c4);
            u32 hi[4]; float lo[4];
#pragma unroll
            for (int e = 0; e < 4; e++) {
                float x = (&av.x)[e];
                hi[e] = tf32r(x);
                lo[e] = x - __uint_as_float(hi[e]);
            }
            *(uint4*)(As_hi + r * PAD + c4) = make_uint4(hi[0], hi[1], hi[2], hi[3]);
            *(uint4*)(As_lo + r * PAD + c4) = make_uint4(tf32r(lo[0]), tf32r(lo[1]),
                                                         tf32r(lo[2]), tf32r(lo[3]));
            float4 bv = *(const float4*)(Bsrc + (size_t)r * FEAT + kc + c4);
#pragma unroll
            for (int e = 0; e < 4; e++) {
                float x = (&bv.x)[e];
                hi[e] = tf32r(x);
                lo[e] = x - __uint_as_float(hi[e]);
            }
            *(uint4*)(Bs_hi + r * PAD + c4) = make_uint4(hi[0], hi[1], hi[2], hi[3]);
            *(uint4*)(Bs_lo + r * PAD + c4) = make_uint4(tf32r(lo[0]), tf32r(lo[1]),
                                                         tf32r(lo[2]), tf32r(lo[3]));
        }
        __syncthreads();

#pragma unroll
        for (int ks = 0; ks < BK / 8; ks++) {
            const int kk = ks * 8;
            u32 ahi[2][4], alo[2][4];
#pragma unroll
            for (int mi = 0; mi < 2; mi++) {
                const u32 off = (u32)(((warp_m * 32 + mi * 16 + a_row_in) * PAD
                                       + kk + a_kd) * 4);
                ldsm4(ahi[mi][0], ahi[mi][1], ahi[mi][2], ahi[mi][3], sAhi + off);
                ldsm4(alo[mi][0], alo[mi][1], alo[mi][2], alo[mi][3], sAlo + off);
            }
            u32 bhi[8][2], blo[8][2];
#pragma unroll
            for (int jp = 0; jp < 4; jp++) {
                const u32 off = (u32)(((warp_n * 64 + jp * 16 + b_row_in) * PAD
                                       + kk + b_kd) * 4);
                ldsm4(bhi[2 * jp][0], bhi[2 * jp][1],
                      bhi[2 * jp + 1][0], bhi[2 * jp + 1][1], sBhi + off);
                ldsm4(blo[2 * jp][0], blo[2 * jp][1],
                      blo[2 * jp + 1][0], blo[2 * jp + 1][1], sBlo + off);
            }
#pragma unroll
            for (int mi = 0; mi < 2; mi++)
#pragma unroll
                for (int j = 0; j < 8; j++) {
                    mma_tf32(acc[mi][j], alo[mi], bhi[j]);
                    mma_tf32(acc[mi][j], ahi[mi], blo[j]);
                    mma_tf32(acc[mi][j], ahi[mi], bhi[j]);
                }
        }
        __syncthreads();
    }

#pragma unroll
    for (int mi = 0; mi < 2; mi++) {
#pragma unroll
        for (int half = 0; half < 2; half++) {
            const int grow = row0 + warp_m * 32 + mi * 16 + g + half * 8;
            if (grow >= n_nodes) continue;
            if (ct < NUM_BASES) {
                float* p = g_proj + (size_t)grow * (NUM_BASES * FEAT) + ct * FEAT
                         + warp_n * 64 + 2 * tig;
#pragma unroll
                for (int j = 0; j < 8; j++)
                    *(float2*)(p + 8 * j) = make_float2(acc[mi][j][2 * half],
                                                        acc[mi][j][2 * half + 1]);
            } else {
                float* p = out + (size_t)grow * FEAT + warp_n * 64 + 2 * tig;
#pragma unroll
                for (int j = 0; j < 8; j++) {
                    const float2 b = *(const float2*)(bias + warp_n * 64 + 2 * tig + 8 * j);
                    *(float2*)(p + 8 * j) = make_float2(acc[mi][j][2 * half] + b.x,
                                                        acc[mi][j][2 * half + 1] + b.y);
                }
            }
        }
    }
}

// ---------------- kernel 2: edge gather/combine/scatter (sorted) ----------------
__global__ void rgcn_edge_kernel(const float* __restrict__ w_comp,
                                 float* __restrict__ out, int n_edges)
{
    const int warp = (blockIdx.x * blockDim.x + threadIdx.x) >> 5;
    const int lane = threadIdx.x & 31;
    if (warp >= n_edges) return;

    const int pk = g_pk[warp];
    const int d  = g_pd[warp];
    const int s  = pk >> 3;
    const int r  = pk & 7;
    const float4 c = *(const float4*)(w_comp + r * NUM_BASES);

    const float* __restrict__ p = g_proj + (size_t)s * (NUM_BASES * FEAT);
    float* __restrict__ o = out + (size_t)d * FEAT;

#pragma unroll
    for (int j = 0; j < 4; j++) {
        const int i = lane + j * 32;
        float m = c.x * p[i]
                + c.y * p[FEAT + i]
                + c.z * p[2 * FEAT + i]
                + c.w * p[3 * FEAT + i];
        atomicAdd(o + i, m);
    }
}

__global__ void rgcn_relu_kernel(float* __restrict__ out, int n4)
{
    int i = blockIdx.x * blockDim.x + threadIdx.x;
    if (i < n4) {
        float4 v = ((float4*)out)[i];
        v.x = fmaxf(v.x, 0.f); v.y = fmaxf(v.y, 0.f);
        v.z = fmaxf(v.z, 0.f); v.w = fmaxf(v.w, 0.f);
        ((float4*)out)[i] = v;
    }
}

extern "C" void kernel_launch(void* const* d_in, const int* in_sizes, int n_in,
                              void* d_out, int out_size)
{
    const float* h      = (const float*)d_in[0];
    const float* weight = (const float*)d_in[1];
    const float* w_comp = (const float*)d_in[2];
    const float* root   = (const float*)d_in[3];
    const float* bias   = (const float*)d_in[4];
    const int*   src    = (const int*)d_in[5];
    const int*   dst    = (const int*)d_in[6];
    const int*   rel    = (const int*)d_in[7];

    const int n_nodes = in_sizes[0] / FEAT;
    const int n_edges = in_sizes[5];
    float* out = (float*)d_out;

    cudaFuncSetAttribute(rgcn_gemm_mma_kernel,
                         cudaFuncAttributeMaxDynamicSharedMemorySize, SM_TOTALB);

    // 0) transpose weights + bucket-sort edges by src (overlappable, tiny)
    dim3 gt(4, 4, NCT);
    transpose_w_kernel<<<gt, dim3(32, 8)>>>(weight, root);
    zero_cnt_kernel<<<1, NB>>>();
    hist_kernel<<<(n_edges + 255) / 256, 256>>>(src, n_edges);
    scan_kernel<<<1, NB>>>();
    scatter_kernel<<<(n_edges + 255) / 256, 256>>>(src, dst, rel, n_edges);

    // 1) split-TF32 tensor-core GEMM: proj (4 bases) + root+bias into out
    dim3 g1((n_nodes + 127) / 128, NCT);
    rgcn_gemm_mma_kernel<<<g1, 256, SM_TOTALB>>>(h, bias, out, n_nodes);

    // 2) edge combine + scatter-add over src-sorted edges
    int blocks_e = (n_edges + 7) / 8;
    rgcn_edge_kernel<<<blocks_e, 256>>>(w_comp, out, n_edges);

    // 3) ReLU
    int n4 = out_size / 4;
    rgcn_relu_kernel<<<(n4 + 255) / 256, 256>>>(out, n4);
}